// round 14
// baseline (speedup 1.0000x reference)
#include <cuda_runtime.h>

// HausdorffDTLoss: B=4, C=2, H=W=256, ALPHA=2 — single-kernel formulation.
// Per block: band of 4 output rows. Row pass (nearest-opposite-bit distances,
// packed u16 fg|bg, sentinel d=1024) computed IN-SMEM for the band's 8 rows
// (4 own + 2 halo each side; out-of-image rows = all-sentinel). Column pass:
// exact integer min of d*d + r^2 over the r<=2 window (exact when best <= 9,
// since any r>=3 candidate >= 9). Rare best>9 lanes fall back to an exact
// scan that recomputes far-row distances straight from the ORIGINAL inputs
// (no cross-block dependency). Finite sums < 2^18 are fp32-exact in the
// reference too; sentinel sums >= 2^20 only win when every row is sentinel,
// reproducing the reference's exact 1e9 / fg-empty guard. field=sqrt(D) then
// field^2 is used as D directly (<= 1 ulp; tolerance 1e-3).

#define HH 256
#define WW 256
#define BB 4
#define SENT 1024u
#define SENTP 0x04000400u
#define NBANDS 64
#define NBLOCKS (NBANDS * BB)

__device__ float g_sum;       // zero at load; last block resets -> replay-safe
__device__ unsigned g_count;  // zero at load; last block resets

// ---------------------------------------------------------------------------
// nearest opposite-valued bit in a 256-bit row mask (8 words in smem)
// ---------------------------------------------------------------------------
__device__ __forceinline__ int nearest_opp(const unsigned* __restrict__ w, int i,
                                           unsigned inv) {
    const int k = i >> 5, bpos = i & 31;
    unsigned m = (w[k] ^ inv) & (0xFFFFFFFFu >> (31 - bpos));
    int L = -1000000, kk = k;
    while (true) {
        if (m) { L = (kk << 5) + 31 - __clz(m); break; }
        if (--kk < 0) break;
        m = w[kk] ^ inv;
    }
    m = (w[k] ^ inv) & (0xFFFFFFFFu << bpos);
    int R = 1000000;
    kk = k;
    while (true) {
        if (m) { R = (kk << 5) + __ffs(m) - 1; break; }
        if (++kk > 7) break;
        m = w[kk] ^ inv;
    }
    return min(i - L, R - i);
}

// ---------------------------------------------------------------------------
// rare exact fallback: recompute far-row plane values from the raw inputs
// ---------------------------------------------------------------------------
__device__ __forceinline__ int pixel_bit(const float* __restrict__ mo,
                                         const float* __restrict__ gt, int b,
                                         int row, int c, int useGt) {
    if (useGt) return gt[(b * HH + row) * WW + c] > 0.5f;
    float a0 = mo[((b * 2 + 0) * HH + row) * WW + c];
    float a1 = mo[((b * 2 + 1) * HH + row) * WW + c];
    return a1 > a0;
}

// distance (in row `row`) from `col` to the nearest pixel NOT in plane bitX
// (= row-pass value for plane bitX at (row,col); 0 if the pixel itself isn't
// in the plane; SENT if the whole row is in the plane).
__device__ __noinline__ unsigned row_plane_d(const float* __restrict__ mo,
                                             const float* __restrict__ gt,
                                             int b, int row, int col, int useGt,
                                             int bitX) {
    if (pixel_bit(mo, gt, b, row, col, useGt) != bitX) return 0u;
#pragma unroll 1
    for (int s = 1; s < 256; ++s) {
        int L = col - s, R = col + s;
        bool okL = (L >= 0), okR = (R < WW);
        if (okL && pixel_bit(mo, gt, b, row, L, useGt) != bitX) return (unsigned)s;
        if (okR && pixel_bit(mo, gt, b, row, R, useGt) != bitX) return (unsigned)s;
        if (!okL && !okR) break;
    }
    return SENT;
}

__device__ __noinline__ unsigned col_extend(const float* __restrict__ mo,
                                            const float* __restrict__ gt, int b,
                                            int i, int col, int useGt, int bitX,
                                            unsigned best) {
#pragma unroll 1
    for (int r = 3; r < 256; ++r) {
        unsigned rr = (unsigned)(r * r);
        if (rr >= best) break;
        int lo = i - r, hi = i + r;
        if (lo >= 0) {
            unsigned d = row_plane_d(mo, gt, b, lo, col, useGt, bitX);
            best = min(best, d * d + rr);
        }
        if (hi < HH) {
            unsigned d = row_plane_d(mo, gt, b, hi, col, useGt, bitX);
            best = min(best, d * d + rr);
        }
    }
    return best;
}

// ---------------------------------------------------------------------------
// fused single kernel: grid=(64 bands, 4 batches), block=256 (t = column).
// ---------------------------------------------------------------------------
__global__ __launch_bounds__(256) void k_hdt(const float* __restrict__ mo,
                                             const float* __restrict__ gt,
                                             float* __restrict__ out) {
    const int band = blockIdx.x;
    const int b = blockIdx.y;
    const int t = threadIdx.x;
    const int row0 = band * 4 - 2;  // band rows: row0 .. row0+7 (own: +2..+5)

    __shared__ unsigned Pm[8][8], Gm[8][8];
    __shared__ uint2 pak[8][WW];  // 16 KB packed row-pass distances
    __shared__ float wsum[8];

    // ---- load the band's pixels (clamped; invalid rows become sentinel) ----
    float m0[8], m1[8], gv[8];
#pragma unroll
    for (int k = 0; k < 8; ++k) {  // 24 independent LDGs in flight
        int r = row0 + k;
        int rc = r < 0 ? 0 : (r > 255 ? 255 : r);
        m0[k] = mo[((b * 2 + 0) * HH + rc) * WW + t];
        m1[k] = mo[((b * 2 + 1) * HH + rc) * WW + t];
        gv[k] = gt[(b * HH + rc) * WW + t];
    }

    // ---- row masks via ballots ----
    unsigned pbits = 0, gbits = 0;
#pragma unroll
    for (int k = 0; k < 8; ++k) {
        bool pb = (m1[k] > m0[k]);  // argmax ties -> channel 0
        bool gb = (gv[k] > 0.5f);
        pbits |= ((unsigned)pb) << k;
        gbits |= ((unsigned)gb) << k;
        unsigned bp = __ballot_sync(0xFFFFFFFFu, pb);
        unsigned bg = __ballot_sync(0xFFFFFFFFu, gb);
        if ((t & 31) == 0) {
            Pm[k][t >> 5] = bp;
            Gm[k][t >> 5] = bg;
        }
    }
    __syncthreads();

    // ---- row pass: packed nearest-opposite-bit distances into smem ----
#pragma unroll
    for (int k = 0; k < 8; ++k) {
        int r = row0 + k;
        uint2 o = make_uint2(SENTP, SENTP);  // out-of-image: all-sentinel
        if ((unsigned)r < 256u) {
            bool pb = (pbits >> k) & 1u;
            bool gb = (gbits >> k) & 1u;
            int pd = nearest_opp(Pm[k], t, pb ? 0xFFFFFFFFu : 0u);
            int gd = nearest_opp(Gm[k], t, gb ? 0xFFFFFFFFu : 0u);
            unsigned ps = (pd > 255) ? SENT : (unsigned)pd;
            unsigned gs = (gd > 255) ? SENT : (unsigned)gd;
            o.x = pb ? ps : (ps << 16);  // fg dist low16, bg dist high16
            o.y = gb ? gs : (gs << 16);
        }
        pak[k][t] = o;
    }
    __syncthreads();

    // ---- column pass + loss for the 4 own rows ----
    uint2 wv[8];
#pragma unroll
    for (int k = 0; k < 8; ++k) wv[k] = pak[k][t];

    float acc = 0.0f;
#pragma unroll
    for (int j = 0; j < 4; ++j) {
        const int i = band * 4 + j;  // global row; own band index j+2
        uint2 v = wv[j + 2];
        bool pbit = (v.x & 0xFFFFu) != 0u;  // own-plane dist >= 1 iff bit set
        bool gbit = (v.y & 0xFFFFu) != 0u;
        int shp = pbit ? 0 : 16;
        int shg = gbit ? 0 : 16;

        unsigned bestP = 0xFFFFFFFFu, bestG = 0xFFFFFFFFu;
#pragma unroll
        for (int q = 0; q < 5; ++q) {
            unsigned rr = (unsigned)((q - 2) * (q - 2));
            unsigned dp = (wv[j + q].x >> shp) & 0xFFFFu;
            unsigned dg = (wv[j + q].y >> shg) & 0xFFFFu;
            bestP = min(bestP, dp * dp + rr);
            bestG = min(bestG, dg * dg + rr);
        }
        if (bestP > 9u) bestP = col_extend(mo, gt, b, i, t, 0, (int)pbit, bestP);
        if (bestG > 9u) bestG = col_extend(mo, gt, b, i, t, 1, (int)gbit, bestG);

        if (pbit != gbit) {  // err == 1, else term is 0
            float pt = (bestP >= (1u << 20)) ? (pbit ? 1.0e9f : 0.0f)
                                             : (float)bestP;
            float gq = (bestG >= (1u << 20)) ? (gbit ? 1.0e9f : 0.0f)
                                             : (float)bestG;
            acc += pt + gq;
        }
    }

    // ---- block reduction + global accumulation ----
#pragma unroll
    for (int off = 16; off > 0; off >>= 1)
        acc += __shfl_down_sync(0xFFFFFFFFu, acc, off);
    if ((t & 31) == 0) wsum[t >> 5] = acc;
    __syncthreads();
    if (t == 0) {
        float s = 0.0f;
#pragma unroll
        for (int j = 0; j < 8; ++j) s += wsum[j];
        atomicAdd(&g_sum, s * (1.0f / 262144.0f));
        __threadfence();
        unsigned done = atomicAdd(&g_count, 1u);
        if (done == NBLOCKS - 1) {  // last block: publish + reset for replay
            float tot = atomicExch(&g_sum, 0.0f);
            out[0] = tot;
            g_count = 0;
        }
    }
}

extern "C" void kernel_launch(void* const* d_in, const int* in_sizes, int n_in,
                              void* d_out, int out_size) {
    const float* mo = (const float*)d_in[0];  // model_output (4,2,256,256) f32
    const float* gt = (const float*)d_in[1];  // ground_truth (4,1,256,256) f32
    float* out = (float*)d_out;

    dim3 grid(NBANDS, BB);
    k_hdt<<<grid, 256>>>(mo, gt, out);
}

// round 15
// speedup vs baseline: 1.1895x; 1.1895x over previous
#include <cuda_runtime.h>

// HausdorffDTLoss: B=4, C=2, H=W=256, ALPHA=2 — single-kernel direct 5x5 EDT.
// loss = mean over pixels of (pred!=gt) * (Dp + Dg), where D = squared
// euclidean distance to the nearest opposite-class pixel (exact integer,
// < 2^18, fp32-exact in the reference as well), with the reference's
// empty-plane semantics: pixel in a class whose opposite is empty -> 1e9
// (bg-empty), pixel NOT in the class with opposite empty -> 0 (fg-empty
// guard). field=sqrt(D) then field^2 is used as D (<= 1 ulp; tol 1e-3).
// The 5x5 bit window gives the exact D whenever D <= 8 (any candidate
// outside the window has dr^2+dc^2 >= 9); rarer pixels (P ~ 2^-24) take an
// exact from-scratch scan of the raw inputs.

#define HH 256
#define WW 256
#define BB 4
#define NBANDS 128           // 2 output rows per band
#define NBLOCKS (NBANDS * BB)
#define BIGD (1 << 20)

__device__ float g_sum;       // zero at load; last block resets -> replay-safe
__device__ unsigned g_count;  // zero at load; last block resets

// ---------------------------------------------------------------------------
// exact fallback: recompute from raw inputs (also handles empty-plane cases)
// ---------------------------------------------------------------------------
__device__ __forceinline__ int pixel_bit(const float* __restrict__ mo,
                                         const float* __restrict__ gt, int b,
                                         int row, int c, int useGt) {
    if (useGt) return gt[(b * HH + row) * WW + c] > 0.5f;
    float a0 = mo[((b * 2 + 0) * HH + row) * WW + c];
    float a1 = mo[((b * 2 + 1) * HH + row) * WW + c];
    return a1 > a0;  // argmax ties -> channel 0
}

// distance in `row` from `col` to nearest pixel with bit != bitX (1024 = none)
__device__ __noinline__ unsigned row_plane_d(const float* __restrict__ mo,
                                             const float* __restrict__ gt,
                                             int b, int row, int col, int useGt,
                                             int bitX) {
    if (pixel_bit(mo, gt, b, row, col, useGt) != bitX) return 0u;
#pragma unroll 1
    for (int s = 1; s < 256; ++s) {
        int L = col - s, R = col + s;
        bool okL = (L >= 0), okR = (R < WW);
        if (okL && pixel_bit(mo, gt, b, row, L, useGt) != bitX) return (unsigned)s;
        if (okR && pixel_bit(mo, gt, b, row, R, useGt) != bitX) return (unsigned)s;
        if (!okL && !okR) break;
    }
    return 1024u;
}

// exact 2D squared distance to nearest opposite-class pixel (>= BIGD if none)
__device__ __noinline__ int exact2d(const float* __restrict__ mo,
                                    const float* __restrict__ gt, int b, int i,
                                    int col, int useGt, int bitX) {
    unsigned best = (unsigned)BIGD;
#pragma unroll 1
    for (int dr = 0; dr < 256; ++dr) {
        unsigned rr = (unsigned)(dr * dr);
        if (rr >= best) break;
        int lo = i - dr, hi = i + dr;
        if (lo >= 0) {
            unsigned d = row_plane_d(mo, gt, b, lo, col, useGt, bitX);
            best = min(best, d * d + rr);
        }
        if (dr > 0 && hi < HH) {
            unsigned d = row_plane_d(mo, gt, b, hi, col, useGt, bitX);
            best = min(best, d * d + rr);
        }
    }
    return (int)best;
}

// ---------------------------------------------------------------------------
// 5-row window min over a padded 10-word bitmask array.
// M[row][w]: bits of image columns, col c at word 1+(c>>5) bit (c&31).
// ---------------------------------------------------------------------------
__device__ __forceinline__ int window5(const unsigned (*M)[10], int jj, int i,
                                       int t, unsigned vm, int xbit) {
    const int k0 = (t + 30) >> 5;
    const int sh = (t + 30) & 31;
    int best = BIGD;
#pragma unroll
    for (int q = 0; q < 5; ++q) {
        const int rr = (q - 2) * (q - 2);
        unsigned lo = M[jj + q][k0];
        unsigned hi = M[jj + q][k0 + 1];
        unsigned w5 = __funnelshift_r(lo, hi, sh);
        unsigned cand = ((xbit ? ~w5 : w5) & 0x1Fu) & vm;
        int wmin = (cand & 4u) ? 0
                   : ((cand & 0xAu) ? 1 : ((cand & 0x11u) ? 4 : BIGD));
        int m = rr + wmin;
        if ((unsigned)(i - 2 + q) >= 256u) m = BIGD;  // out-of-image row
        best = min(best, m);
    }
    return best;
}

// ---------------------------------------------------------------------------
// fused kernel: grid=(128 bands, 4 batches), block=256 (t = column).
// Band = 2 output rows; loads 6 rows (2 halo each side, clamped).
// ---------------------------------------------------------------------------
__global__ __launch_bounds__(256) void k_hdt(const float* __restrict__ mo,
                                             const float* __restrict__ gt,
                                             float* __restrict__ out) {
    const int band = blockIdx.x;
    const int b = blockIdx.y;
    const int t = threadIdx.x;
    const int r0 = band * 2;

    __shared__ unsigned PM[6][10], GM[6][10];
    __shared__ float wsum[8];

    // zero the pad words (cols <0 and >255); values masked by vm anyway
    if (t < 24) {
        int row = t % 6, which = (t / 6) & 1, msk = t / 12;
        if (msk == 0) PM[row][which ? 9 : 0] = 0u;
        else          GM[row][which ? 9 : 0] = 0u;
    }

    // load 6 rows (clamped at image borders; invalid rows neutralized later)
    float m0[6], m1[6], gv[6];
#pragma unroll
    for (int k = 0; k < 6; ++k) {  // 18 independent LDGs in flight
        int r = r0 + k - 2;
        int rc = r < 0 ? 0 : (r > 255 ? 255 : r);
        m0[k] = mo[((b * 2 + 0) * HH + rc) * WW + t];
        m1[k] = mo[((b * 2 + 1) * HH + rc) * WW + t];
        gv[k] = gt[(b * HH + rc) * WW + t];
    }

    // ballots -> row bitmasks in smem; keep own bits in a register
    unsigned pbits = 0, gbits = 0;
#pragma unroll
    for (int k = 0; k < 6; ++k) {
        bool pb = (m1[k] > m0[k]);  // argmax ties -> channel 0
        bool gb = (gv[k] > 0.5f);
        pbits |= ((unsigned)pb) << k;
        gbits |= ((unsigned)gb) << k;
        unsigned bp = __ballot_sync(0xFFFFFFFFu, pb);
        unsigned bg = __ballot_sync(0xFFFFFFFFu, gb);
        if ((t & 31) == 0) {
            PM[k][1 + (t >> 5)] = bp;
            GM[k][1 + (t >> 5)] = bg;
        }
    }
    __syncthreads();

    // column-validity mask for the 5-bit window (borders have no candidates)
    unsigned vm = 0x1Fu;
    if (t < 2) vm &= 0x1Fu << (2 - t);
    if (t > 253) vm &= 0x1Fu >> (t - 253);

    float acc = 0.0f;
#pragma unroll
    for (int jj = 0; jj < 2; ++jj) {
        const int i = r0 + jj;       // global row
        const int k = jj + 2;        // band index of own row
        int pbit = (pbits >> k) & 1;
        int gbit = (gbits >> k) & 1;
        if (pbit != gbit) {  // err == 1, else term is 0
            int bestP = window5(PM, jj, i, t, vm, pbit);
            int bestG = window5(GM, jj, i, t, vm, gbit);
            if (bestP > 8) bestP = exact2d(mo, gt, b, i, t, 0, pbit);
            if (bestG > 8) bestG = exact2d(mo, gt, b, i, t, 1, gbit);
            float pt = (bestP >= BIGD) ? (pbit ? 1.0e9f : 0.0f) : (float)bestP;
            float gq = (bestG >= BIGD) ? (gbit ? 1.0e9f : 0.0f) : (float)bestG;
            acc += pt + gq;
        }
    }

    // block reduction + global accumulation (last block publishes & resets)
#pragma unroll
    for (int o = 16; o > 0; o >>= 1) acc += __shfl_down_sync(0xFFFFFFFFu, acc, o);
    if ((t & 31) == 0) wsum[t >> 5] = acc;
    __syncthreads();
    if (t == 0) {
        float s = 0.0f;
#pragma unroll
        for (int j = 0; j < 8; ++j) s += wsum[j];
        atomicAdd(&g_sum, s * (1.0f / 262144.0f));
        __threadfence();
        unsigned done = atomicAdd(&g_count, 1u);
        if (done == NBLOCKS - 1) {
            out[0] = atomicExch(&g_sum, 0.0f);
            g_count = 0;
        }
    }
}

extern "C" void kernel_launch(void* const* d_in, const int* in_sizes, int n_in,
                              void* d_out, int out_size) {
    const float* mo = (const float*)d_in[0];  // model_output (4,2,256,256) f32
    const float* gt = (const float*)d_in[1];  // ground_truth (4,1,256,256) f32
    float* out = (float*)d_out;

    dim3 grid(NBANDS, BB);
    k_hdt<<<grid, 256>>>(mo, gt, out);
}

// round 16
// speedup vs baseline: 1.4571x; 1.2250x over previous
#include <cuda_runtime.h>

// HausdorffDTLoss: B=4, C=2, H=W=256, ALPHA=2 — two tiny passes on bitmasks.
// loss = mean over pixels of (pred!=gt) * (Dp + Dg), D = exact squared
// distance to the nearest opposite-class pixel (integer < 2^18, fp32-exact in
// the reference as well), with the reference's empty-plane semantics (1e9 for
// in-class pixels when the opposite class is empty; 0 otherwise — fg-empty
// guard). field=sqrt(D) then field^2 is used as D (<=1 ulp; tol 1e-3).
// K1 reads the float inputs ONCE and stores only per-row ballot bitmasks.
// K2 computes D from the bitmasks: a 5x5 bit window is exact whenever D <= 8
// (any candidate outside has dr^2+dc^2 >= 9); rare pixels (P ~ 2^-24) take an
// exact full mask scan.

#define HH 256
#define WW 256
#define BB 4
#define BIGD (1 << 20)

// per row: [mask 0=pred,1=gt][10 words]; words 1..8 real, 0 and 9 zero pads
__device__ unsigned g_mask[BB][HH][2][10];

// ---------------------------------------------------------------------------
// K1: mask pass, 2 rows per block. grid=(128, 4), block=256. Zeroes out[0].
// ---------------------------------------------------------------------------
__global__ __launch_bounds__(256) void k_mask(const float* __restrict__ mo,
                                              const float* __restrict__ gt,
                                              float* __restrict__ out) {
    const int rp = blockIdx.x;  // row pair
    const int b = blockIdx.y;
    const int t = threadIdx.x;

    float m0[2], m1[2], gv[2];
#pragma unroll
    for (int k = 0; k < 2; ++k) {  // 6 independent LDGs in flight
        int r = rp * 2 + k;
        m0[k] = mo[((b * 2 + 0) * HH + r) * WW + t];
        m1[k] = mo[((b * 2 + 1) * HH + r) * WW + t];
        gv[k] = gt[(b * HH + r) * WW + t];
    }
#pragma unroll
    for (int k = 0; k < 2; ++k) {
        int r = rp * 2 + k;
        bool pb = (m1[k] > m0[k]);  // argmax ties -> channel 0
        bool gb = (gv[k] > 0.5f);
        unsigned bp = __ballot_sync(0xFFFFFFFFu, pb);
        unsigned bg = __ballot_sync(0xFFFFFFFFu, gb);
        if ((t & 31) == 0) {
            g_mask[b][r][0][1 + (t >> 5)] = bp;
            g_mask[b][r][1][1 + (t >> 5)] = bg;
        }
    }
    // pad words: 2 rows x 2 masks x 2 pads = 8 stores
    if (t < 8) {
        int r = rp * 2 + (t & 1);
        int m = (t >> 1) & 1;
        int w = (t & 4) ? 9 : 0;
        g_mask[b][r][m][w] = 0u;
    }
    if (rp == 0 && b == 0 && t == 0) out[0] = 0.0f;
}

// ---------------------------------------------------------------------------
// nearest opposite-valued bit in a row mask (8 words at ptr[0..7])
// ---------------------------------------------------------------------------
__device__ __forceinline__ int nearest_opp_g(const unsigned* __restrict__ w,
                                             int i, unsigned inv) {
    const int k = i >> 5, bpos = i & 31;
    unsigned m = (w[k] ^ inv) & (0xFFFFFFFFu >> (31 - bpos));
    int L = -1000000, kk = k;
    while (true) {
        if (m) { L = (kk << 5) + 31 - __clz(m); break; }
        if (--kk < 0) break;
        m = w[kk] ^ inv;
    }
    m = (w[k] ^ inv) & (0xFFFFFFFFu << bpos);
    int R = 1000000;
    kk = k;
    while (true) {
        if (m) { R = (kk << 5) + __ffs(m) - 1; break; }
        if (++kk > 7) break;
        m = w[kk] ^ inv;
    }
    return min(i - L, R - i);
}

// exact 2D squared distance from the masks (>= BIGD if plane-opposite empty)
__device__ __noinline__ unsigned exact2d(int b, int i, int col, int m,
                                         int bitX) {
    const unsigned inv = bitX ? 0xFFFFFFFFu : 0u;
    unsigned best = (unsigned)BIGD;
#pragma unroll 1
    for (int dr = 0; dr < 256; ++dr) {
        unsigned rr = (unsigned)(dr * dr);
        if (rr >= best) break;
        int lo = i - dr, hi = i + dr;
        if (lo >= 0) {
            int d = nearest_opp_g(&g_mask[b][lo][m][1], col, inv);
            unsigned du = (d > 255) ? 1024u : (unsigned)d;
            best = min(best, du * du + rr);
        }
        if (dr > 0 && hi < HH) {
            int d = nearest_opp_g(&g_mask[b][hi][m][1], col, inv);
            unsigned du = (d > 255) ? 1024u : (unsigned)d;
            best = min(best, du * du + rr);
        }
    }
    return best;
}

// ---------------------------------------------------------------------------
// K2: window pass on bitmasks only. grid=(64 bands, 4 batches), block=256.
// Band = 4 output rows; smem holds 8 mask rows x 2 masks x 10 words.
// ---------------------------------------------------------------------------
__global__ __launch_bounds__(256) void k_win(float* __restrict__ out) {
    const int band = blockIdx.x;
    const int b = blockIdx.y;
    const int t = threadIdx.x;
    const int r0 = band * 4;

    __shared__ unsigned SM[8][2][10];  // 640 B
    __shared__ float wsum[8];

    if (t < 160) {  // one word per thread
        int row = t / 20, rem = t % 20, m = rem / 10, w = rem % 10;
        int gr = r0 - 2 + row;
        int rc = gr < 0 ? 0 : (gr > 255 ? 255 : gr);  // invalid rows masked later
        SM[row][m][w] = g_mask[b][rc][m][w];
    }
    __syncthreads();

    // extract the 5-bit column strip for each of the 8 window rows, per mask
    const int k0 = (t + 30) >> 5;
    const int sh = (t + 30) & 31;
    unsigned sp[8], sg[8];
#pragma unroll
    for (int k = 0; k < 8; ++k) {
        sp[k] = __funnelshift_r(SM[k][0][k0], SM[k][0][k0 + 1], sh) & 0x1Fu;
        sg[k] = __funnelshift_r(SM[k][1][k0], SM[k][1][k0 + 1], sh) & 0x1Fu;
    }

    // column-validity mask (border columns lack left/right candidates)
    unsigned vm = 0x1Fu;
    if (t < 2) vm &= 0x1Fu << (2 - t);
    if (t > 253) vm &= 0x1Fu >> (t - 253);

    float acc = 0.0f;
#pragma unroll
    for (int j = 0; j < 4; ++j) {
        const int i = r0 + j;  // global row; own strip index j+2
        int pbit = (sp[j + 2] >> 2) & 1;
        int gbit = (sg[j + 2] >> 2) & 1;
        if (pbit != gbit) {  // err == 1, else term is 0
            unsigned bestP = BIGD, bestG = BIGD;
#pragma unroll
            for (int q = 0; q < 5; ++q) {
                const unsigned rr = (unsigned)((q - 2) * (q - 2));
                unsigned cp = ((pbit ? ~sp[j + q] : sp[j + q]) & 0x1Fu) & vm;
                unsigned cg = ((gbit ? ~sg[j + q] : sg[j + q]) & 0x1Fu) & vm;
                unsigned wp = (cp & 4u) ? 0u
                              : ((cp & 0xAu) ? 1u : ((cp & 0x11u) ? 4u : BIGD));
                unsigned wg = (cg & 4u) ? 0u
                              : ((cg & 0xAu) ? 1u : ((cg & 0x11u) ? 4u : BIGD));
                unsigned mp = rr + wp, mg = rr + wg;
                if ((unsigned)(i - 2 + q) >= 256u) { mp = BIGD; mg = BIGD; }
                bestP = min(bestP, mp);
                bestG = min(bestG, mg);
            }
            if (bestP > 8u) bestP = exact2d(b, i, t, 0, pbit);
            if (bestG > 8u) bestG = exact2d(b, i, t, 1, gbit);

            float pt = (bestP >= BIGD) ? (pbit ? 1.0e9f : 0.0f) : (float)bestP;
            float gq = (bestG >= BIGD) ? (gbit ? 1.0e9f : 0.0f) : (float)bestG;
            acc += pt + gq;
        }
    }

    // deterministic block reduction, then one REDG add of the scaled partial
#pragma unroll
    for (int o = 16; o > 0; o >>= 1) acc += __shfl_down_sync(0xFFFFFFFFu, acc, o);
    if ((t & 31) == 0) wsum[t >> 5] = acc;
    __syncthreads();
    if (t == 0) {
        float s = 0.0f;
#pragma unroll
        for (int j = 0; j < 8; ++j) s += wsum[j];
        atomicAdd(out, s * (1.0f / 262144.0f));
    }
}

extern "C" void kernel_launch(void* const* d_in, const int* in_sizes, int n_in,
                              void* d_out, int out_size) {
    const float* mo = (const float*)d_in[0];  // model_output (4,2,256,256) f32
    const float* gt = (const float*)d_in[1];  // ground_truth (4,1,256,256) f32
    float* out = (float*)d_out;

    dim3 grid1(128, BB);
    k_mask<<<grid1, 256>>>(mo, gt, out);
    dim3 grid2(64, BB);
    k_win<<<grid2, 256>>>(out);
}

// round 17
// speedup vs baseline: 1.4624x; 1.0036x over previous
#include <cuda_runtime.h>

// HausdorffDTLoss: B=4, C=2, H=W=256, ALPHA=2 — bitmask passes, word-parallel.
// loss = mean over pixels of (pred!=gt) * (Dp + Dg); D = exact squared
// distance to the nearest opposite-class pixel (integer, fp32-exact in the
// reference as well), with the reference's empty-plane semantics (1e9 for
// in-class pixels when the opposite class is empty; 0 otherwise).
// field=sqrt(D) then field^2 is used as D (<=1 ulp; tolerance 1e-3).
// K1: floats -> per-row ballot bitmasks (read inputs exactly once).
// K2: word-parallel 5x5 window on the masks. For 32 pixels at once:
// candidate indicator for offset (dr,dc) = shift(mask_row, dc) ^ center_word.
// D <= 8 is exact in the window (any outside candidate >= 9); the cost
// classes are D in {1,2,4,5,8}. Unresolved pixels (P ~ 2^-24) take an exact
// full mask scan, which also reproduces the empty-plane guard.

#define HH 256
#define WW 256
#define BB 4
#define BIGD (1u << 20)

// per row: [mask 0=pred,1=gt][10 words]; words 1..8 real, 0 and 9 zero pads
__device__ unsigned g_mask[BB][HH][2][10];

// ---------------------------------------------------------------------------
// K1: mask pass, 2 rows per block. grid=(128, 4), block=256. Zeroes out[0].
// ---------------------------------------------------------------------------
__global__ __launch_bounds__(256) void k_mask(const float* __restrict__ mo,
                                              const float* __restrict__ gt,
                                              float* __restrict__ out) {
    const int rp = blockIdx.x;  // row pair
    const int b = blockIdx.y;
    const int t = threadIdx.x;

    float m0[2], m1[2], gv[2];
#pragma unroll
    for (int k = 0; k < 2; ++k) {  // 6 independent LDGs in flight
        int r = rp * 2 + k;
        m0[k] = mo[((b * 2 + 0) * HH + r) * WW + t];
        m1[k] = mo[((b * 2 + 1) * HH + r) * WW + t];
        gv[k] = gt[(b * HH + r) * WW + t];
    }
#pragma unroll
    for (int k = 0; k < 2; ++k) {
        int r = rp * 2 + k;
        bool pb = (m1[k] > m0[k]);  // argmax ties -> channel 0
        bool gb = (gv[k] > 0.5f);
        unsigned bp = __ballot_sync(0xFFFFFFFFu, pb);
        unsigned bg = __ballot_sync(0xFFFFFFFFu, gb);
        if ((t & 31) == 0) {
            g_mask[b][r][0][1 + (t >> 5)] = bp;
            g_mask[b][r][1][1 + (t >> 5)] = bg;
        }
    }
    if (t < 8) {  // zero pad words: 2 rows x 2 masks x 2 pads
        int r = rp * 2 + (t & 1);
        int m = (t >> 1) & 1;
        int w = (t & 4) ? 9 : 0;
        g_mask[b][r][m][w] = 0u;
    }
    if (rp == 0 && b == 0 && t == 0) out[0] = 0.0f;
}

// ---------------------------------------------------------------------------
// nearest opposite-valued bit in a row mask (8 words at ptr[0..7])
// ---------------------------------------------------------------------------
__device__ __forceinline__ int nearest_opp_g(const unsigned* __restrict__ w,
                                             int i, unsigned inv) {
    const int k = i >> 5, bpos = i & 31;
    unsigned m = (w[k] ^ inv) & (0xFFFFFFFFu >> (31 - bpos));
    int L = -1000000, kk = k;
    while (true) {
        if (m) { L = (kk << 5) + 31 - __clz(m); break; }
        if (--kk < 0) break;
        m = w[kk] ^ inv;
    }
    m = (w[k] ^ inv) & (0xFFFFFFFFu << bpos);
    int R = 1000000;
    kk = k;
    while (true) {
        if (m) { R = (kk << 5) + __ffs(m) - 1; break; }
        if (++kk > 7) break;
        m = w[kk] ^ inv;
    }
    return min(i - L, R - i);
}

// exact 2D squared distance from the masks (>= BIGD if opposite class empty)
__device__ __noinline__ unsigned exact2d(int b, int i, int col, int m,
                                         int bitX) {
    const unsigned inv = bitX ? 0xFFFFFFFFu : 0u;
    unsigned best = BIGD;
#pragma unroll 1
    for (int dr = 0; dr < 256; ++dr) {
        unsigned rr = (unsigned)(dr * dr);
        if (rr >= best) break;
        int lo = i - dr, hi = i + dr;
        if (lo >= 0) {
            int d = nearest_opp_g(&g_mask[b][lo][m][1], col, inv);
            unsigned du = (d > 255) ? 1024u : (unsigned)d;
            best = min(best, du * du + rr);
        }
        if (dr > 0 && hi < HH) {
            int d = nearest_opp_g(&g_mask[b][hi][m][1], col, inv);
            unsigned du = (d > 255) ? 1024u : (unsigned)d;
            best = min(best, du * du + rr);
        }
    }
    return best;
}

// ---------------------------------------------------------------------------
// per-plane cost-class masks from 5 rows x 3 padded words
// X[q][k]: words w-1,w,w+1 (padded indices) of mask row i-2+q. C: center word.
// A[0..4] = pixels with an opposite-class candidate at cost 1,2,4,5,8.
// ---------------------------------------------------------------------------
__device__ __forceinline__ void plane_classes(const unsigned X[5][3],
                                              const unsigned rv[5], unsigned C,
                                              unsigned cmL1, unsigned cmL2,
                                              unsigned cmR1, unsigned cmR2,
                                              unsigned A[5]) {
    unsigned M[5][5];
#pragma unroll
    for (int q = 0; q < 5; ++q) {
        unsigned x0 = X[q][0], x1 = X[q][1], x2 = X[q][2];
        unsigned sm2 = __funnelshift_l(x0, x1, 2);  // candidate at c-2
        unsigned sm1 = __funnelshift_l(x0, x1, 1);  // candidate at c-1
        unsigned sp1 = __funnelshift_r(x1, x2, 1);  // candidate at c+1
        unsigned sp2 = __funnelshift_r(x1, x2, 2);  // candidate at c+2
        unsigned v = rv[q];
        M[q][0] = (sm2 ^ C) & v & cmL2;
        M[q][1] = (sm1 ^ C) & v & cmL1;
        M[q][2] = (x1 ^ C) & v;
        M[q][3] = (sp1 ^ C) & v & cmR1;
        M[q][4] = (sp2 ^ C) & v & cmR2;
    }
    A[0] = M[2][1] | M[2][3] | M[1][2] | M[3][2];                      // D=1
    A[1] = M[1][1] | M[1][3] | M[3][1] | M[3][3];                      // D=2
    A[2] = M[2][0] | M[2][4] | M[0][2] | M[4][2];                      // D=4
    A[3] = M[0][1] | M[0][3] | M[4][1] | M[4][3] | M[1][0] | M[1][4] |
           M[3][0] | M[3][4];                                          // D=5
    A[4] = M[0][0] | M[0][4] | M[4][0] | M[4][4];                      // D=8
}

// ---------------------------------------------------------------------------
// K2: word-parallel window pass. grid=(32 bands, 4 batches), block=64.
// Thread = (row within 8-row band) x (word 0..7): 32 pixels per thread.
// ---------------------------------------------------------------------------
__global__ __launch_bounds__(64) void k_win(float* __restrict__ out) {
    const int t = threadIdx.x;
    const int b = blockIdx.y;
    const int w = t & 7;                       // word (cols 32w..32w+31)
    const int i = blockIdx.x * 8 + (t >> 3);   // global row

    // load 5 mask rows x 2 masks x 3 padded words (w, w+1, w+2)
    unsigned Pw[5][3], Gw[5][3], rv[5];
#pragma unroll
    for (int q = 0; q < 5; ++q) {
        int r = i - 2 + q;
        rv[q] = ((unsigned)r < 256u) ? 0xFFFFFFFFu : 0u;
        int rc = r < 0 ? 0 : (r > 255 ? 255 : r);
#pragma unroll
        for (int k = 0; k < 3; ++k) {
            Pw[q][k] = g_mask[b][rc][0][w + k];
            Gw[q][k] = g_mask[b][rc][1][w + k];
        }
    }

    // column-boundary masks (pad words are zero, which would alias "opposite")
    const unsigned cmL1 = (w == 0) ? 0xFFFFFFFEu : 0xFFFFFFFFu;
    const unsigned cmL2 = (w == 0) ? 0xFFFFFFFCu : 0xFFFFFFFFu;
    const unsigned cmR1 = (w == 7) ? 0x7FFFFFFFu : 0xFFFFFFFFu;
    const unsigned cmR2 = (w == 7) ? 0x3FFFFFFFu : 0xFFFFFFFFu;

    const unsigned Cp = Pw[2][1], Cg = Gw[2][1];
    const unsigned E = Cp ^ Cg;  // pixels with err == 1

    unsigned Ap[5], Ag[5];
    plane_classes(Pw, rv, Cp, cmL1, cmL2, cmR1, cmR2, Ap);
    plane_classes(Gw, rv, Cg, cmL1, cmL2, cmR1, cmR2, Ag);

    const unsigned cost[5] = {1u, 2u, 4u, 5u, 8u};
    unsigned isum = 0;
    unsigned remP = E, remG = E;
#pragma unroll
    for (int k = 0; k < 5; ++k) {
        isum += cost[k] * (unsigned)__popc(Ap[k] & remP);
        remP &= ~Ap[k];
        isum += cost[k] * (unsigned)__popc(Ag[k] & remG);
        remG &= ~Ag[k];
    }
    float acc = (float)isum;

    // rare exact fallback (also covers the empty-plane 1e9/0 guard)
    while (remP) {
        int j = __ffs(remP) - 1;
        remP &= remP - 1;
        int bit = (Cp >> j) & 1;
        unsigned d = exact2d(b, i, w * 32 + j, 0, bit);
        acc += (d >= BIGD) ? (bit ? 1.0e9f : 0.0f) : (float)d;
    }
    while (remG) {
        int j = __ffs(remG) - 1;
        remG &= remG - 1;
        int bit = (Cg >> j) & 1;
        unsigned d = exact2d(b, i, w * 32 + j, 1, bit);
        acc += (d >= BIGD) ? (bit ? 1.0e9f : 0.0f) : (float)d;
    }

    // block reduction (64 threads) + one atomic per block
    __shared__ float ws[2];
#pragma unroll
    for (int o = 16; o > 0; o >>= 1) acc += __shfl_down_sync(0xFFFFFFFFu, acc, o);
    if ((t & 31) == 0) ws[t >> 5] = acc;
    __syncthreads();
    if (t == 0) atomicAdd(out, (ws[0] + ws[1]) * (1.0f / 262144.0f));
}

extern "C" void kernel_launch(void* const* d_in, const int* in_sizes, int n_in,
                              void* d_out, int out_size) {
    const float* mo = (const float*)d_in[0];  // model_output (4,2,256,256) f32
    const float* gt = (const float*)d_in[1];  // ground_truth (4,1,256,256) f32
    float* out = (float*)d_out;

    dim3 grid1(128, BB);
    k_mask<<<grid1, 256>>>(mo, gt, out);
    dim3 grid2(32, BB);
    k_win<<<grid2, 64>>>(out);
}